// round 8
// baseline (speedup 1.0000x reference)
#include <cuda_runtime.h>
#include <cuda_fp16.h>

#define BB 64
#define II 4096
#define CC 32
#define DD 16
#define KD 16

#define NI 16                 // i's per fused CTA
#define NCH2 (II / NI)        // 256 chunks

#define WCH1H 4098            // Wf chunk1 base (halves): word 2049 == 1 mod 32
#define XCH1H 258             // xf chunk1 base (halves): word 129  == 1 mod 32

// Scratch (static device globals; no runtime allocation)
__device__ float g_spart2[(size_t)NCH2 * BB * 512];   // 33.5 MB: [chunk][row64][col512]
__device__ float g_V[BB * CC * DD];                   // Vsum, layout [b][c][D] == [b][n]

// ============================================================================
// Fused routing pass: recompute u[b,i,n] = sum_d x[b,i,d] * W[i,n,d] on tensor
// cores, then softmax_c(u . V) weighting, accumulate s over NI i's in registers.
// CTA = (chunk, bhalf): 256 threads = 8 warps; warp (mt 0..1, ng 0..3):
// local rows 16mt+lr, +8 (32 rows = b-half); cols 128ng + 8nt + 2lc (512 n).
// Fragment/fill layouts identical to the validated R7 kernel.
// ============================================================================

#define FILL_SMEM_FROM_REGS()                                                   \
    {                                                                           \
        _Pragma("unroll")                                                       \
        for (int q = 0; q < 8; q++) {                                           \
            int slot = tid + q * 256;                                           \
            int n = slot >> 2, d0 = (slot & 3) * 4;                             \
            int base = (d0 >= 8 ? WCH1H : 0) + n * 8 + (d0 & 7);                \
            *(__half2*)&Wf[base]     = __floats2half2_rn(wreg[q].x, wreg[q].y); \
            *(__half2*)&Wf[base + 2] = __floats2half2_rn(wreg[q].z, wreg[q].w); \
        }                                                                       \
        if (tid < 128) {                                                        \
            int row = tid >> 2, d0 = (tid & 3) * 4;                             \
            int base = (d0 >= 8 ? XCH1H : 0) + row * 8 + (d0 & 7);              \
            *(__half2*)&xf[base]     = __floats2half2_rn(xreg.x, xreg.y);       \
            *(__half2*)&xf[base + 2] = __floats2half2_rn(xreg.z, xreg.w);       \
        }                                                                       \
    }

#define LOAD_REGS(ii)                                                           \
    {                                                                           \
        const float4* w4 = (const float4*)(w + (size_t)(ii) * 8192);            \
        _Pragma("unroll")                                                       \
        for (int q = 0; q < 8; q++) wreg[q] = w4[tid + q * 256];                \
        if (tid < 128) {                                                        \
            int row = tid >> 2;                                                 \
            xreg = *(const float4*)(x + ((size_t)(b_base + row) * II + (ii)) * KD \
                                    + (tid & 3) * 4);                           \
        }                                                                       \
    }

#define DO_MMA(cdst)                                                            \
    {                                                                           \
        int r = 16 * mt + lr;                                                   \
        unsigned a0 = *(unsigned*)&xf[r * 8 + 2 * lc];                          \
        unsigned a1 = *(unsigned*)&xf[(r + 8) * 8 + 2 * lc];                    \
        unsigned a2 = *(unsigned*)&xf[XCH1H + r * 8 + 2 * lc];                  \
        unsigned a3 = *(unsigned*)&xf[XCH1H + (r + 8) * 8 + 2 * lc];            \
        _Pragma("unroll")                                                       \
        for (int nt = 0; nt < 16; nt++) {                                       \
            int nn = 128 * ng + 8 * nt + lr;                                    \
            unsigned b0 = *(unsigned*)&Wf[nn * 8 + 2 * lc];                     \
            unsigned b1 = *(unsigned*)&Wf[WCH1H + nn * 8 + 2 * lc];             \
            asm volatile(                                                       \
                "mma.sync.aligned.m16n8k16.row.col.f32.f16.f16.f32 "            \
                "{%0,%1,%2,%3}, {%4,%5,%6,%7}, {%8,%9}, {%0,%1,%2,%3};"         \
                : "+f"(cdst[nt][0]), "+f"(cdst[nt][1]),                         \
                  "+f"(cdst[nt][2]), "+f"(cdst[nt][3])                          \
                : "r"(a0), "r"(a1), "r"(a2), "r"(a3), "r"(b0), "r"(b1));        \
        }                                                                       \
    }

#define FLUSH_PARTIALS(src, scale)                                              \
    {                                                                           \
        float* dst = g_spart2 + (size_t)chunk * (BB * 512);                     \
        _Pragma("unroll")                                                       \
        for (int nt = 0; nt < 16; nt++) {                                       \
            int col = 128 * ng + 8 * nt + 2 * lc;                               \
            _Pragma("unroll")                                                   \
            for (int rp = 0; rp < 2; rp++) {                                    \
                int rowg = b_base + 16 * mt + lr + 8 * rp;                      \
                float2 v2 = make_float2(src[nt][rp * 2] * (scale),              \
                                        src[nt][rp * 2 + 1] * (scale));         \
                *(float2*)&dst[rowg * 512 + col] = v2;                          \
            }                                                                   \
        }                                                                       \
    }

// ---------- pass 0: cij = 1/32 uniform; mma accumulates across i directly ----------
__global__ __launch_bounds__(256) void fused_pass0(
    const float* __restrict__ x, const float* __restrict__ w) {
    __shared__ __half Wf[WCH1H + 4096];   // 512n x 16d fp16, chunked
    __shared__ __half xf[XCH1H + 256];    // 32b  x 16d fp16, chunked

    const int tid   = threadIdx.x;
    const int chunk = blockIdx.x >> 1;
    const int bhalf = blockIdx.x & 1;
    const int b_base = bhalf * 32;
    const int i0    = chunk * NI;
    const int warp  = tid >> 5;
    const int l     = tid & 31;
    const int lr    = l >> 2, lc = l & 3;
    const int mt    = warp >> 2, ng = warp & 3;

    float4 wreg[8];
    float4 xreg;
    LOAD_REGS(i0);

    float sacc[16][4];
    #pragma unroll
    for (int nt = 0; nt < 16; nt++)
        { sacc[nt][0] = 0.f; sacc[nt][1] = 0.f; sacc[nt][2] = 0.f; sacc[nt][3] = 0.f; }

    for (int j = 0; j < NI; j++) {
        FILL_SMEM_FROM_REGS();
        __syncthreads();                       // smem ready
        if (j + 1 < NI) LOAD_REGS(i0 + j + 1); // overlaps mma
        DO_MMA(sacc);                          // accumulate across i: s1 = sum_i u
        __syncthreads();                       // mma reads done before next fill
    }
    FLUSH_PARTIALS(sacc, (1.0f / 32.0f));
}

// ---------- pass 1/2: full softmax routing against V ----------
__global__ __launch_bounds__(256) void fused_pass12(
    const float* __restrict__ x, const float* __restrict__ w) {
    __shared__ __half Wf[WCH1H + 4096];
    __shared__ __half xf[XCH1H + 256];
    __shared__ float  Lg[32 * 33];    // logits [row][cap], pitch 33
    __shared__ float  Cij[32 * 33];   // softmax weights

    const int tid   = threadIdx.x;
    const int chunk = blockIdx.x >> 1;
    const int bhalf = blockIdx.x & 1;
    const int b_base = bhalf * 32;
    const int i0    = chunk * NI;
    const int warp  = tid >> 5;
    const int l     = tid & 31;
    const int lr    = l >> 2, lc = l & 3;
    const int mt    = warp >> 2, ng = warp & 3;

    // V fragment registers (fp16x2): Vr[rp][k][ntp] = V[row(rp), 8ng+k, ntp*8+2lc + {0,1}]
    __half2 Vr[2][8][2];
    #pragma unroll
    for (int rp = 0; rp < 2; rp++) {
        int b = b_base + 16 * mt + lr + 8 * rp;
        #pragma unroll
        for (int k = 0; k < 8; k++) {
            int cg = 8 * ng + k;
            #pragma unroll
            for (int ntp = 0; ntp < 2; ntp++) {
                float2 vv = *(const float2*)&g_V[((b * CC + cg) << 4) + ntp * 8 + 2 * lc];
                Vr[rp][k][ntp] = __floats2half2_rn(vv.x, vv.y);
            }
        }
    }

    float4 wreg[8];
    float4 xreg;
    LOAD_REGS(i0);

    float sacc[16][4];
    #pragma unroll
    for (int nt = 0; nt < 16; nt++)
        { sacc[nt][0] = 0.f; sacc[nt][1] = 0.f; sacc[nt][2] = 0.f; sacc[nt][3] = 0.f; }

    for (int j = 0; j < NI; j++) {
        FILL_SMEM_FROM_REGS();
        __syncthreads();                       // A: smem ready
        if (j + 1 < NI) LOAD_REGS(i0 + j + 1);

        float cacc[16][4];
        #pragma unroll
        for (int nt = 0; nt < 16; nt++)
            { cacc[nt][0] = 0.f; cacc[nt][1] = 0.f; cacc[nt][2] = 0.f; cacc[nt][3] = 0.f; }
        DO_MMA(cacc);

        // logit partials: p[rp][k] = sum over this thread's 4 D-slots, then quad-reduce
        float p[2][8];
        #pragma unroll
        for (int rp = 0; rp < 2; rp++) {
            #pragma unroll
            for (int k = 0; k < 8; k++) {
                float pr = 0.0f;
                #pragma unroll
                for (int ntp = 0; ntp < 2; ntp++) {
                    float2 vv = __half22float2(Vr[rp][k][ntp]);
                    int nt = 2 * k + ntp;
                    pr = fmaf(cacc[nt][rp * 2],     vv.x, pr);
                    pr = fmaf(cacc[nt][rp * 2 + 1], vv.y, pr);
                }
                p[rp][k] = pr;
            }
        }
        #pragma unroll
        for (int rp = 0; rp < 2; rp++)
            #pragma unroll
            for (int k = 0; k < 8; k++) {
                p[rp][k] += __shfl_xor_sync(0xffffffffu, p[rp][k], 1);
                p[rp][k] += __shfl_xor_sync(0xffffffffu, p[rp][k], 2);
            }
        if (lc == 0) {
            #pragma unroll
            for (int rp = 0; rp < 2; rp++) {
                int row = 16 * mt + lr + 8 * rp;
                #pragma unroll
                for (int k = 0; k < 8; k++)
                    Lg[row * 33 + 8 * ng + k] = p[rp][k];
            }
        }
        __syncthreads();                       // B: logits complete (also guards Wf reuse)

        // softmax over 32 capsules: warps 0..3, thread = (row, 8-c slice)
        if (tid < 128) {
            int row = tid >> 2, c0 = (tid & 3) * 8;
            float lv[8];
            float m = -1e30f;
            #pragma unroll
            for (int k = 0; k < 8; k++) {
                lv[k] = Lg[row * 33 + c0 + k];
                m = fmaxf(m, lv[k]);
            }
            m = fmaxf(m, __shfl_xor_sync(0xffffffffu, m, 1));
            m = fmaxf(m, __shfl_xor_sync(0xffffffffu, m, 2));
            float sum = 0.0f;
            #pragma unroll
            for (int k = 0; k < 8; k++) { lv[k] = __expf(lv[k] - m); sum += lv[k]; }
            sum += __shfl_xor_sync(0xffffffffu, sum, 1);
            sum += __shfl_xor_sync(0xffffffffu, sum, 2);
            float inv = 1.0f / sum;
            #pragma unroll
            for (int k = 0; k < 8; k++) Cij[row * 33 + c0 + k] = lv[k] * inv;
        }
        __syncthreads();                       // C: Cij ready

        // s += cij * u
        #pragma unroll
        for (int nt = 0; nt < 16; nt++) {
            int cap = 8 * ng + (nt >> 1);
            #pragma unroll
            for (int rp = 0; rp < 2; rp++) {
                int row = 16 * mt + lr + 8 * rp;
                float cij = Cij[row * 33 + cap];
                sacc[nt][rp * 2]     = fmaf(cij, cacc[nt][rp * 2],     sacc[nt][rp * 2]);
                sacc[nt][rp * 2 + 1] = fmaf(cij, cacc[nt][rp * 2 + 1], sacc[nt][rp * 2 + 1]);
            }
        }
        // no extra sync needed: next fill touches only Wf/xf (reads done pre-B);
        // next Cij write happens after next B, by which time all warps passed here.
    }
    FLUSH_PARTIALS(sacc, 1.0f);
}

// ---------- reduce partials + squash: thread per (b, n); 16-lane shfl for |s|^2 ----------
__global__ void reduce_squash(float* __restrict__ out, int pass) {
    int t = blockIdx.x * blockDim.x + threadIdx.x;   // 0..32767: b = t>>9, n = t&511
    float s = 0.0f;
    #pragma unroll 8
    for (int ch = 0; ch < NCH2; ch++)
        s += g_spart2[(size_t)ch * (BB * 512) + t];

    float sq = s * s;
    #pragma unroll
    for (int off = 1; off < 16; off <<= 1)
        sq += __shfl_xor_sync(0xffffffffu, sq, off);   // sums over the 16 D's of capsule

    float f = 1.0f / ((1.0f + sq) * sqrtf(sq + 1e-9f));
    float v = s * f;

    if (pass == 0)      g_V[t] = v;
    else if (pass == 1) g_V[t] += v;
    else                out[t] = v;
}

extern "C" void kernel_launch(void* const* d_in, const int* in_sizes, int n_in,
                              void* d_out, int out_size) {
    const float* x = (const float*)d_in[0];
    const float* w = (const float*)d_in[1];
    float* out = (float*)d_out;

    fused_pass0<<<NCH2 * 2, 256>>>(x, w);
    reduce_squash<<<128, 256>>>(out, 0);

    fused_pass12<<<NCH2 * 2, 256>>>(x, w);
    reduce_squash<<<128, 256>>>(out, 1);

    fused_pass12<<<NCH2 * 2, 256>>>(x, w);
    reduce_squash<<<128, 256>>>(out, 2);
}